// round 7
// baseline (speedup 1.0000x reference)
#include <cuda_runtime.h>
#include <cuda_bf16.h>
#include <cstdint>

// Problem constants
#define B_    128
#define Q_    30
#define D_    200
#define E_    300
#define C_    128
#define QROWS 3840
#define DROWS 25600
#define NROWS 29440          // 230 * 128
#define NCOLS 768
#define KP    320            // padded K per split-pass

typedef unsigned long long u64;

// ================= f32x2 helpers =================
__device__ __forceinline__ u64 dupf(float x) {
    u64 r; unsigned xi = __float_as_uint(x);
    asm("mov.b64 %0, {%1, %1};" : "=l"(r) : "r"(xi));
    return r;
}
__device__ __forceinline__ u64 packf(float lo, float hi) {
    u64 r; unsigned a = __float_as_uint(lo), b = __float_as_uint(hi);
    asm("mov.b64 %0, {%1, %2};" : "=l"(r) : "r"(a), "r"(b));
    return r;
}
__device__ __forceinline__ void unpackf(u64 v, float& lo, float& hi) {
    unsigned a, b;
    asm("mov.b64 {%0, %1}, %2;" : "=r"(a), "=r"(b) : "l"(v));
    lo = __uint_as_float(a); hi = __uint_as_float(b);
}
__device__ __forceinline__ void ffma2(u64& d, u64 a, u64 b) {
    asm("fma.rn.f32x2 %0, %1, %2, %0;" : "+l"(d) : "l"(a), "l"(b));
}
__device__ __forceinline__ u64 add2(u64 a, u64 b) {
    u64 r; asm("add.rn.f32x2 %0, %1, %2;" : "=l"(r) : "l"(a), "l"(b)); return r;
}
__device__ __forceinline__ u64 mul2(u64 a, u64 b) {
    u64 r; asm("mul.rn.f32x2 %0, %1, %2;" : "=l"(r) : "l"(a), "l"(b)); return r;
}
__device__ __forceinline__ float ex2f(float x) {
    float r; asm("ex2.approx.f32 %0, %1;" : "=f"(r) : "f"(x)); return r;
}
__device__ __forceinline__ void cpasync16(uint32_t sdst, const void* gsrc) {
    asm volatile("cp.async.cg.shared.global [%0], [%1], 16;" :: "r"(sdst), "l"(gsrc));
}
__device__ __forceinline__ uint32_t smem_u32(const void* p) {
    uint32_t a;
    asm("{ .reg .u64 t; cvta.to.shared.u64 t, %1; cvt.u32.u64 %0, t; }" : "=r"(a) : "l"(p));
    return a;
}
__device__ __forceinline__ void ldmatrix_x4(uint32_t* r, uint32_t saddr) {
    asm volatile("ldmatrix.sync.aligned.m8n8.x4.shared.b16 {%0,%1,%2,%3}, [%4];"
                 : "=r"(r[0]), "=r"(r[1]), "=r"(r[2]), "=r"(r[3]) : "r"(saddr));
}
__device__ __forceinline__ void mma_bf16(float* c, const uint32_t* a,
                                         uint32_t b0, uint32_t b1) {
    asm volatile("mma.sync.aligned.m16n8k16.row.col.f32.bf16.bf16.f32 "
                 "{%0,%1,%2,%3}, {%4,%5,%6,%7}, {%8,%9}, {%0,%1,%2,%3};"
                 : "+f"(c[0]), "+f"(c[1]), "+f"(c[2]), "+f"(c[3])
                 : "r"(a[0]), "r"(a[1]), "r"(a[2]), "r"(a[3]), "r"(b0), "r"(b1));
}

// ================= device scratch =================
__device__ __nv_bfloat16 g_Ahi[(size_t)NROWS * KP];
__device__ __nv_bfloat16 g_Alo[(size_t)NROWS * KP];
__device__ __nv_bfloat16 g_Whi[(size_t)NCOLS * KP];
__device__ __nv_bfloat16 g_Wlo[(size_t)NCOLS * KP];
__device__ float g_P[(size_t)NROWS * NCOLS];
__device__ float g_qn[3 * (size_t)QROWS * C_];
__device__ float g_dn[3 * (size_t)DROWS * C_];
__device__ float g_feats[B_ * 99];

// ================= pack kernel (W + A merged) =================
#define WBLOCKS ((NCOLS * KP + 255) / 256)
#define ABLOCKS ((NROWS * (KP / 4) + 255) / 256)
__global__ void pack_all(const float* __restrict__ w1,
                         const float* __restrict__ w2,
                         const float* __restrict__ w3,
                         const float* __restrict__ emb,
                         const int* __restrict__ qtok,
                         const int* __restrict__ dtok)
{
    if (blockIdx.x < WBLOCKS) {
        int idx = blockIdx.x * 256 + threadIdx.x;
        if (idx >= NCOLS * KP) return;
        int n = idx / KP, k = idx % KP;
        float v = 0.f;
        if (k < E_) {
            if (n < 128)       v = w1[n * E_ + k];
            else if (n < 384) { int u = n - 128; v = w2[(u & 127) * (E_ * 2) + k * 2 + (u >> 7)]; }
            else              { int u = n - 384; v = w3[(u & 127) * (E_ * 3) + k * 3 + (u >> 7)]; }
        }
        __nv_bfloat16 h = __float2bfloat16(v);
        __nv_bfloat16 l = __float2bfloat16(v - __bfloat162float(h));
        g_Whi[idx] = h; g_Wlo[idx] = l;
    } else {
        int idx = (blockIdx.x - WBLOCKS) * 256 + threadIdx.x;
        if (idx >= NROWS * (KP / 4)) return;
        int r = idx / (KP / 4), g = idx % (KP / 4);
        int k = g * 4;
        float4 v = make_float4(0.f, 0.f, 0.f, 0.f);
        if (k < E_) {
            int tok = (r < QROWS) ? qtok[r] : dtok[r - QROWS];
            v = *(const float4*)(emb + (size_t)tok * E_ + k);
        }
        float vv[4] = {v.x, v.y, v.z, v.w};
        u64 hw = 0, lw = 0;
#pragma unroll
        for (int i = 0; i < 4; i++) {
            __nv_bfloat16 h = __float2bfloat16(vv[i]);
            __nv_bfloat16 l = __float2bfloat16(vv[i] - __bfloat162float(h));
            hw |= (u64)(*(unsigned short*)&h) << (16 * i);
            lw |= (u64)(*(unsigned short*)&l) << (16 * i);
        }
        *(u64*)(g_Ahi + (size_t)r * KP + k) = hw;
        *(u64*)(g_Alo + (size_t)r * KP + k) = lw;
    }
}

// ================= K1: HMMA GEMM  P = A' @ W'^T  (bf16 split, K'=960) =================
// CTA tile 128x256, 8 warps (2x4), warp tile 64x64, KC=32, 3-stage cp.async (R4 config).
#define KC        32
#define NCHUNK    30
#define A_BYTES   (128 * 64)       // 128 rows * 64B (32 bf16)
#define B_BYTES   (256 * 64)
#define STAGE_B   (A_BYTES + B_BYTES)
#define K1_SMEM   (3 * STAGE_B)    // 73728

__device__ __forceinline__ uint32_t swz(int row, int ch) {
    return (uint32_t)(row * 64 + ((ch ^ ((row >> 1) & 3)) << 4));
}

__global__ __launch_bounds__(256, 1) void k1h()
{
    extern __shared__ char smem[];
    const uint32_t sb = smem_u32(smem);
    const int tid = threadIdx.x;
    const int lane = tid & 31;
    const int wid = tid >> 5;
    const int warp_m = wid & 1;        // 0..1
    const int warp_n = wid >> 1;       // 0..3
    const int bm0 = blockIdx.x * 128;
    const int bn0 = blockIdx.y * 256;

    float c[4][8][4];
#pragma unroll
    for (int i = 0; i < 4; i++)
#pragma unroll
        for (int j = 0; j < 8; j++)
#pragma unroll
            for (int k = 0; k < 4; k++) c[i][j][k] = 0.f;

    auto load_stage = [&](int chunk, int st) {
        const int pass = chunk / 10;
        const int kloc = (chunk % 10) * KC;
        const __nv_bfloat16* As = (pass == 2) ? g_Alo : g_Ahi;
        const __nv_bfloat16* Bs = (pass == 1) ? g_Wlo : g_Whi;
        const uint32_t aB = sb + st * STAGE_B;
        const uint32_t bB = aB + A_BYTES;
#pragma unroll
        for (int j = 0; j < 2; j++) {
            int u = tid + j * 256;             // A: 128 rows x 4 chunks
            int row = u >> 2, ch = u & 3;
            cpasync16(aB + swz(row, ch), As + (size_t)(bm0 + row) * KP + kloc + ch * 8);
        }
#pragma unroll
        for (int j = 0; j < 4; j++) {
            int u = tid + j * 256;             // B: 256 rows x 4 chunks
            int row = u >> 2, ch = u & 3;
            cpasync16(bB + swz(row, ch), Bs + (size_t)(bn0 + row) * KP + kloc + ch * 8);
        }
        asm volatile("cp.async.commit_group;");
    };

    load_stage(0, 0);
    load_stage(1, 1);

    const int rit = (lane & 7) + ((lane >> 3) & 1) * 8;

    for (int cidx = 0; cidx < NCHUNK; cidx++) {
        const int st = cidx % 3;
        if (cidx < NCHUNK - 1) asm volatile("cp.async.wait_group 1;");
        else                   asm volatile("cp.async.wait_group 0;");
        __syncthreads();
        if (cidx + 2 < NCHUNK) load_stage(cidx + 2, (cidx + 2) % 3);

        const uint32_t aB = sb + st * STAGE_B;
        const uint32_t bB = aB + A_BYTES;
#pragma unroll
        for (int ks = 0; ks < 2; ks++) {
            const int kch = ks * 2 + (lane >> 4);
            uint32_t a[4][4], b[4][4];
#pragma unroll
            for (int mi = 0; mi < 4; mi++) {
                int r = warp_m * 64 + mi * 16 + rit;
                ldmatrix_x4(a[mi], aB + swz(r, kch));
            }
#pragma unroll
            for (int nj = 0; nj < 4; nj++) {
                int r = warp_n * 64 + nj * 16 + rit;
                ldmatrix_x4(b[nj], bB + swz(r, kch));
            }
#pragma unroll
            for (int mi = 0; mi < 4; mi++)
#pragma unroll
                for (int nj = 0; nj < 4; nj++) {
                    mma_bf16(c[mi][2 * nj],     a[mi], b[nj][0], b[nj][2]);
                    mma_bf16(c[mi][2 * nj + 1], a[mi], b[nj][1], b[nj][3]);
                }
        }
        __syncthreads();
    }

#pragma unroll
    for (int mi = 0; mi < 4; mi++) {
        const int r0 = bm0 + warp_m * 64 + mi * 16 + (lane >> 2);
#pragma unroll
        for (int nj = 0; nj < 4; nj++) {
#pragma unroll
            for (int h = 0; h < 2; h++) {
                const float* cc = c[mi][2 * nj + h];
                const int col = bn0 + warp_n * 64 + nj * 16 + h * 8 + (lane & 3) * 2;
                *(float2*)&g_P[(size_t)r0 * NCOLS + col]       = make_float2(cc[0], cc[1]);
                *(float2*)&g_P[(size_t)(r0 + 8) * NCOLS + col] = make_float2(cc[2], cc[3]);
            }
        }
    }
}

// ================= K2: tap-combine + bias + ReLU + L2-normalize =================
__global__ void k2_combine(const float* __restrict__ cb1,
                           const float* __restrict__ cb2,
                           const float* __restrict__ cb3)
{
    const int r = blockIdx.x;
    const int c = threadIdx.x;
    int l, L, rr;
    const bool isq = (r < QROWS);
    if (isq) { rr = r;          l = r % Q_;  L = Q_; }
    else     { rr = r - QROWS;  l = rr % D_; L = D_; }

    const float* Pr = g_P + (size_t)r * NCOLS;
    float v1 = cb1[c] + Pr[c];
    float v2 = cb2[c] + Pr[128 + c];
    float v3 = cb3[c] + Pr[384 + c];
    if (l + 1 < L) { v2 += Pr[NCOLS + 256 + c]; v3 += Pr[NCOLS + 512 + c]; }
    if (l + 2 < L) { v3 += Pr[2 * NCOLS + 640 + c]; }
    v1 = fmaxf(v1, 0.f); v2 = fmaxf(v2, 0.f); v3 = fmaxf(v3, 0.f);

    float s1 = v1 * v1, s2 = v2 * v2, s3 = v3 * v3;
#pragma unroll
    for (int o = 16; o; o >>= 1) {
        s1 += __shfl_xor_sync(0xffffffffu, s1, o);
        s2 += __shfl_xor_sync(0xffffffffu, s2, o);
        s3 += __shfl_xor_sync(0xffffffffu, s3, o);
    }
    __shared__ float sred[3][4];
    const int lane = c & 31, w = c >> 5;
    if (lane == 0) { sred[0][w] = s1; sred[1][w] = s2; sred[2][w] = s3; }
    __syncthreads();
    float ss1 = sred[0][0] + sred[0][1] + sred[0][2] + sred[0][3];
    float ss2 = sred[1][0] + sred[1][1] + sred[1][2] + sred[1][3];
    float ss3 = sred[2][0] + sred[2][1] + sred[2][2] + sred[2][3];
    float n1 = v1 * (1.0f / (sqrtf(ss1) + 1e-13f));
    float n2 = v2 * (1.0f / (sqrtf(ss2) + 1e-13f));
    float n3 = v3 * (1.0f / (sqrtf(ss3) + 1e-13f));

    if (isq) {
        g_qn[((size_t)0 * QROWS + rr) * C_ + c] = n1;
        g_qn[((size_t)1 * QROWS + rr) * C_ + c] = n2;
        g_qn[((size_t)2 * QROWS + rr) * C_ + c] = n3;
    } else {
        g_dn[((size_t)0 * DROWS + rr) * C_ + c] = n1;
        g_dn[((size_t)1 * DROWS + rr) * C_ + c] = n2;
        g_dn[((size_t)2 * DROWS + rr) * C_ + c] = n3;
    }
}

// ================= K3: fused cosine GEMM + chain-RBF + log pooling =================
// 256 threads: warp = 4 q rows (ty = warp id), lanes tx = 32 d-groups of 8 (256 d, one chunk).
// smem floats: dsT 128x256 quad-swizzled | qsT 128x36 | spk 32x11 | qm 32 | dm 256
#define K3_DS   0
#define K3_QS   32768
#define K3_SPK  37376
#define K3_QM   37728
#define K3_DM   37760
#define K3_SMEM ((37760 + 256) * 4)

__global__ __launch_bounds__(256, 1) void k3_pool(const int* __restrict__ qtok,
                                                  const int* __restrict__ dtok)
{
    extern __shared__ float sm[];
    float* dsT = sm + K3_DS;
    float* qsT = sm + K3_QS;
    float* spk = sm + K3_SPK;
    float* qm  = sm + K3_QM;
    float* dmm = sm + K3_DM;

    const int b = blockIdx.x, pair = blockIdx.y;
    const int qi3 = pair / 3, dj3 = pair % 3;
    const int tid = threadIdx.x;
    const int tx = tid & 31;      // d group (8 d each)
    const int ty = tid >> 5;      // warp id = q group (4 q each)
    const int q0 = ty * 4;

    if (tid < 32) qm[tid] = (tid < Q_ && qtok[b * Q_ + tid] > 0) ? 1.f : 0.f;
    // FIX: all 256 d-mask entries must be written (R6 bug: 224..255 were left uninitialized)
    dmm[tid] = (tid < D_ && dtok[b * D_ + tid] > 0) ? 1.f : 0.f;

    // q tile transposed: qsT[c][q], rows of 36 floats; 256 threads = 2 halves
    const float* qbase = g_qn + ((size_t)qi3 * QROWS + b * Q_) * C_;
    {
        int cch = tid & 127, half = tid >> 7;
        float* qrow = qsT + cch * 36;
        for (int i = half * 15; i < half * 15 + 15; i++)
            qrow[i] = qbase[(size_t)i * C_ + cch];
        qrow[30 + half] = 0.f;
    }

    // d tile: coalesced row loads, quad-swizzled transpose store
    const float* dbase = g_dn + ((size_t)dj3 * DROWS + b * D_) * C_;
    {
        int cch = tid & 127, dh = tid >> 7;
#pragma unroll 4
        for (int i = 0; i < 128; i++) {
            int d = 2 * i + dh;
            float v = (d < D_) ? dbase[(size_t)d * C_ + cch] : 0.f;
            dsT[cch * 256 + ((((d >> 2) ^ (cch & 63)) << 2) | (d & 3))] = v;
        }
    }

    // accumulators
    float pk0[4] = {0.f, 0.f, 0.f, 0.f};
    u64 pk56[4] = {0,0,0,0}, pk47[4] = {0,0,0,0}, pk38[4] = {0,0,0,0},
        pk29[4] = {0,0,0,0}, pk110[4] = {0,0,0,0};

    const float K20 = 28.853901f;       //  20*log2(e)
    const float AW  = -72.134754f;      // -50*log2(e)
    const float A0  = -7.2134754e8f;    // -5e5*log2(e)
    const u64 C4  = dupf(1.8315639e-2f);    // exp(-4)
    const u64 C8  = dupf(3.3546262e-4f);    // exp(-8)
    const u64 C12 = dupf(6.1442124e-6f);    // exp(-12)
    const u64 C16 = dupf(1.1253517e-7f);    // exp(-16)

    __syncthreads();

    float qmv[4];
#pragma unroll
    for (int i = 0; i < 4; i++) qmv[i] = qm[q0 + i];
    float dmv[8];
#pragma unroll
    for (int j = 0; j < 8; j++) dmv[j] = dmm[tx * 8 + j];

    // ---- cosine GEMM: cs[4 q][4 d-pairs] over K=128 ----
    u64 cs[4][4];
#pragma unroll
    for (int i = 0; i < 4; i++)
#pragma unroll
        for (int j = 0; j < 4; j++) cs[i][j] = 0ull;

#pragma unroll 4
    for (int k = 0; k < 128; k++) {
        float4 qv = *(const float4*)(qsT + k * 36 + q0);
        const float* drow = dsT + k * 256;
        float4 db0 = *(const float4*)(drow + ((((2 * tx)     ^ (k & 63))) << 2));
        float4 db1 = *(const float4*)(drow + ((((2 * tx + 1) ^ (k & 63))) << 2));
        u64 dp[4] = { ((const u64*)&db0)[0], ((const u64*)&db0)[1],
                      ((const u64*)&db1)[0], ((const u64*)&db1)[1] };
        u64 qd[4] = { dupf(qv.x), dupf(qv.y), dupf(qv.z), dupf(qv.w) };
#pragma unroll
        for (int i = 0; i < 4; i++)
#pragma unroll
            for (int j = 0; j < 4; j++)
                ffma2(cs[i][j], qd[i], dp[j]);
    }

    // ---- RBF chains ----
#pragma unroll
    for (int i = 0; i < 4; i++) {
#pragma unroll
        for (int j = 0; j < 4; j++) {
            float clo, chi;
            unpackf(cs[i][j], clo, chi);
            float cpair[2] = {clo, chi};
#pragma unroll
            for (int h = 0; h < 2; h++) {
                float m = qmv[i] * dmv[2 * j + h];
                float c = cpair[h] * m;
                float arg = c * K20;
                float t  = ex2f(arg);
                float ti = ex2f(-arg);
                u64 tt = packf(t, ti);
                float dl = c - 0.1f;
                float gl = ex2f(dl * dl * AW);
                u64 ab = packf(gl, gl * ti);     // (exp(-50(c-.1)^2), exp(-50(c+.1)^2))
                u64 m2 = dupf(m);
                ffma2(pk56[i], m2, ab);
                ab = mul2(ab, tt); ab = mul2(ab, C4);  ffma2(pk47[i], m2, ab);
                ab = mul2(ab, tt); ab = mul2(ab, C8);  ffma2(pk38[i], m2, ab);
                ab = mul2(ab, tt); ab = mul2(ab, C12); ffma2(pk29[i], m2, ab);
                ab = mul2(ab, tt); ab = mul2(ab, C16); ffma2(pk110[i], m2, ab);
                float d1 = c - 1.f;
                pk0[i] = fmaf(m, ex2f(d1 * d1 * A0), pk0[i]);
            }
        }
    }

    // ---- full-warp reduction over 32 lanes (warp owns its 4 q rows) ----
#pragma unroll
    for (int o = 1; o <= 16; o <<= 1) {
#pragma unroll
        for (int i = 0; i < 4; i++) {
            pk0[i]  += __shfl_xor_sync(0xffffffffu, pk0[i], o);
            pk56[i]  = add2(pk56[i],  __shfl_xor_sync(0xffffffffu, pk56[i], o));
            pk47[i]  = add2(pk47[i],  __shfl_xor_sync(0xffffffffu, pk47[i], o));
            pk38[i]  = add2(pk38[i],  __shfl_xor_sync(0xffffffffu, pk38[i], o));
            pk29[i]  = add2(pk29[i],  __shfl_xor_sync(0xffffffffu, pk29[i], o));
            pk110[i] = add2(pk110[i], __shfl_xor_sync(0xffffffffu, pk110[i], o));
        }
    }
    if (tx == 0) {
#pragma unroll
        for (int i = 0; i < 4; i++) {
            float lo, hi;
            float* row = spk + (q0 + i) * 11;
            row[0] = pk0[i];
            unpackf(pk56[i],  lo, hi); row[5] = lo; row[6]  = hi;
            unpackf(pk47[i],  lo, hi); row[4] = lo; row[7]  = hi;
            unpackf(pk38[i],  lo, hi); row[3] = lo; row[8]  = hi;
            unpackf(pk29[i],  lo, hi); row[2] = lo; row[9]  = hi;
            unpackf(pk110[i], lo, hi); row[1] = lo; row[10] = hi;
        }
    }
    __syncthreads();

    if (tid < 11) {
        float f = 0.f;
        for (int q = 0; q < Q_; q++)
            f += logf(fmaxf(spk[q * 11 + tid], 1e-10f)) * 0.01f * qm[q];
        g_feats[(b * 9 + pair) * 11 + tid] = f;
    }
}

// ================= K4: final dense =================
__global__ void k4_out(const float* __restrict__ dw, float* __restrict__ out)
{
    int b = threadIdx.x;
    float f = 0.f;
#pragma unroll
    for (int j = 0; j < 99; j++) f += g_feats[b * 99 + j] * dw[j];
    out[b] = f;
}

// ================= launch =================
extern "C" void kernel_launch(void* const* d_in, const int* in_sizes, int n_in,
                              void* d_out, int out_size)
{
    (void)in_sizes; (void)n_in; (void)out_size;
    const int*   qtok = (const int*)d_in[0];
    const int*   dtok = (const int*)d_in[1];
    const float* emb  = (const float*)d_in[2];
    const float* w1   = (const float*)d_in[3];
    const float* w2   = (const float*)d_in[4];
    const float* w3   = (const float*)d_in[5];
    const float* cb1  = (const float*)d_in[6];
    const float* cb2  = (const float*)d_in[7];
    const float* cb3  = (const float*)d_in[8];
    const float* dw   = (const float*)d_in[9];
    float* out = (float*)d_out;

    cudaFuncSetAttribute(k1h, cudaFuncAttributeMaxDynamicSharedMemorySize, K1_SMEM);
    cudaFuncSetAttribute(k3_pool, cudaFuncAttributeMaxDynamicSharedMemorySize, K3_SMEM);

    pack_all<<<WBLOCKS + ABLOCKS, 256>>>(w1, w2, w3, emb, qtok, dtok);
    k1h<<<dim3(230, 3), 256, K1_SMEM>>>();
    k2_combine<<<NROWS, 128>>>(cb1, cb2, cb3);
    k3_pool<<<dim3(128, 9), 256, K3_SMEM>>>(qtok, dtok);
    k4_out<<<1, 128>>>(dw, out);
}

// round 8
// speedup vs baseline: 1.3736x; 1.3736x over previous
#include <cuda_runtime.h>
#include <cuda_bf16.h>
#include <cstdint>

// Problem constants
#define B_    128
#define Q_    30
#define D_    200
#define E_    300
#define C_    128
#define QROWS 3840
#define DROWS 25600
#define NROWS 29440          // 230 * 128
#define NCOLS 768
#define KP    320            // padded K per split-pass

typedef unsigned long long u64;

// ================= f32x2 / misc helpers =================
__device__ __forceinline__ u64 dupf(float x) {
    u64 r; unsigned xi = __float_as_uint(x);
    asm("mov.b64 %0, {%1, %1};" : "=l"(r) : "r"(xi));
    return r;
}
__device__ __forceinline__ u64 packf(float lo, float hi) {
    u64 r; unsigned a = __float_as_uint(lo), b = __float_as_uint(hi);
    asm("mov.b64 %0, {%1, %2};" : "=l"(r) : "r"(a), "r"(b));
    return r;
}
__device__ __forceinline__ void unpackf(u64 v, float& lo, float& hi) {
    unsigned a, b;
    asm("mov.b64 {%0, %1}, %2;" : "=r"(a), "=r"(b) : "l"(v));
    lo = __uint_as_float(a); hi = __uint_as_float(b);
}
__device__ __forceinline__ void ffma2(u64& d, u64 a, u64 b) {
    asm("fma.rn.f32x2 %0, %1, %2, %0;" : "+l"(d) : "l"(a), "l"(b));
}
__device__ __forceinline__ u64 add2(u64 a, u64 b) {
    u64 r; asm("add.rn.f32x2 %0, %1, %2;" : "=l"(r) : "l"(a), "l"(b)); return r;
}
__device__ __forceinline__ u64 mul2(u64 a, u64 b) {
    u64 r; asm("mul.rn.f32x2 %0, %1, %2;" : "=l"(r) : "l"(a), "l"(b)); return r;
}
__device__ __forceinline__ float ex2f(float x) {
    float r; asm("ex2.approx.f32 %0, %1;" : "=f"(r) : "f"(x)); return r;
}
__device__ __forceinline__ void cpasync16(uint32_t sdst, const void* gsrc) {
    asm volatile("cp.async.cg.shared.global [%0], [%1], 16;" :: "r"(sdst), "l"(gsrc));
}
__device__ __forceinline__ void cpasync16z(uint32_t sdst, const void* gsrc, int sz) {
    asm volatile("cp.async.cg.shared.global [%0], [%1], 16, %2;" :: "r"(sdst), "l"(gsrc), "r"(sz));
}
__device__ __forceinline__ uint32_t smem_u32(const void* p) {
    uint32_t a;
    asm("{ .reg .u64 t; cvta.to.shared.u64 t, %1; cvt.u32.u64 %0, t; }" : "=r"(a) : "l"(p));
    return a;
}
__device__ __forceinline__ void ldmatrix_x4(uint32_t* r, uint32_t saddr) {
    asm volatile("ldmatrix.sync.aligned.m8n8.x4.shared.b16 {%0,%1,%2,%3}, [%4];"
                 : "=r"(r[0]), "=r"(r[1]), "=r"(r[2]), "=r"(r[3]) : "r"(saddr));
}
__device__ __forceinline__ void mma_bf16(float* c, const uint32_t* a,
                                         uint32_t b0, uint32_t b1) {
    asm volatile("mma.sync.aligned.m16n8k16.row.col.f32.bf16.bf16.f32 "
                 "{%0,%1,%2,%3}, {%4,%5,%6,%7}, {%8,%9}, {%0,%1,%2,%3};"
                 : "+f"(c[0]), "+f"(c[1]), "+f"(c[2]), "+f"(c[3])
                 : "r"(a[0]), "r"(a[1]), "r"(a[2]), "r"(a[3]), "r"(b0), "r"(b1));
}

// ================= device scratch =================
__device__ __nv_bfloat16 g_Ahi[(size_t)NROWS * KP];
__device__ __nv_bfloat16 g_Alo[(size_t)NROWS * KP];
__device__ __nv_bfloat16 g_Whi[(size_t)NCOLS * KP];
__device__ __nv_bfloat16 g_Wlo[(size_t)NCOLS * KP];
__device__ float g_P[(size_t)NROWS * NCOLS];
__device__ __nv_bfloat16 g_qnh[3 * (size_t)QROWS * C_];
__device__ __nv_bfloat16 g_qnl[3 * (size_t)QROWS * C_];
__device__ __nv_bfloat16 g_dnh[3 * (size_t)DROWS * C_];
__device__ __nv_bfloat16 g_dnl[3 * (size_t)DROWS * C_];
__device__ float g_feats[B_ * 99];

// ================= pack kernel (W + A merged) =================
#define WBLOCKS ((NCOLS * KP + 255) / 256)
#define ABLOCKS ((NROWS * (KP / 4) + 255) / 256)
__global__ void pack_all(const float* __restrict__ w1,
                         const float* __restrict__ w2,
                         const float* __restrict__ w3,
                         const float* __restrict__ emb,
                         const int* __restrict__ qtok,
                         const int* __restrict__ dtok)
{
    if (blockIdx.x < WBLOCKS) {
        int idx = blockIdx.x * 256 + threadIdx.x;
        if (idx >= NCOLS * KP) return;
        int n = idx / KP, k = idx % KP;
        float v = 0.f;
        if (k < E_) {
            if (n < 128)       v = w1[n * E_ + k];
            else if (n < 384) { int u = n - 128; v = w2[(u & 127) * (E_ * 2) + k * 2 + (u >> 7)]; }
            else              { int u = n - 384; v = w3[(u & 127) * (E_ * 3) + k * 3 + (u >> 7)]; }
        }
        __nv_bfloat16 h = __float2bfloat16(v);
        __nv_bfloat16 l = __float2bfloat16(v - __bfloat162float(h));
        g_Whi[idx] = h; g_Wlo[idx] = l;
    } else {
        int idx = (blockIdx.x - WBLOCKS) * 256 + threadIdx.x;
        if (idx >= NROWS * (KP / 4)) return;
        int r = idx / (KP / 4), g = idx % (KP / 4);
        int k = g * 4;
        float4 v = make_float4(0.f, 0.f, 0.f, 0.f);
        if (k < E_) {
            int tok = (r < QROWS) ? qtok[r] : dtok[r - QROWS];
            v = *(const float4*)(emb + (size_t)tok * E_ + k);
        }
        float vv[4] = {v.x, v.y, v.z, v.w};
        u64 hw = 0, lw = 0;
#pragma unroll
        for (int i = 0; i < 4; i++) {
            __nv_bfloat16 h = __float2bfloat16(vv[i]);
            __nv_bfloat16 l = __float2bfloat16(vv[i] - __bfloat162float(h));
            hw |= (u64)(*(unsigned short*)&h) << (16 * i);
            lw |= (u64)(*(unsigned short*)&l) << (16 * i);
        }
        *(u64*)(g_Ahi + (size_t)r * KP + k) = hw;
        *(u64*)(g_Alo + (size_t)r * KP + k) = lw;
    }
}

// ================= K1: HMMA GEMM  P = A' @ W'^T  (bf16 split, K'=960) =================
#define KC        32
#define NCHUNK    30
#define A_BYTES   (128 * 64)
#define B_BYTES   (256 * 64)
#define STAGE_B   (A_BYTES + B_BYTES)
#define K1_SMEM   (3 * STAGE_B)

__device__ __forceinline__ uint32_t swz(int row, int ch) {
    return (uint32_t)(row * 64 + ((ch ^ ((row >> 1) & 3)) << 4));
}

__global__ __launch_bounds__(256, 1) void k1h()
{
    extern __shared__ char smem[];
    const uint32_t sb = smem_u32(smem);
    const int tid = threadIdx.x;
    const int lane = tid & 31;
    const int wid = tid >> 5;
    const int warp_m = wid & 1;
    const int warp_n = wid >> 1;
    const int bm0 = blockIdx.x * 128;
    const int bn0 = blockIdx.y * 256;

    float c[4][8][4];
#pragma unroll
    for (int i = 0; i < 4; i++)
#pragma unroll
        for (int j = 0; j < 8; j++)
#pragma unroll
            for (int k = 0; k < 4; k++) c[i][j][k] = 0.f;

    auto load_stage = [&](int chunk, int st) {
        const int pass = chunk / 10;
        const int kloc = (chunk % 10) * KC;
        const __nv_bfloat16* As = (pass == 2) ? g_Alo : g_Ahi;
        const __nv_bfloat16* Bs = (pass == 1) ? g_Wlo : g_Whi;
        const uint32_t aB = sb + st * STAGE_B;
        const uint32_t bB = aB + A_BYTES;
#pragma unroll
        for (int j = 0; j < 2; j++) {
            int u = tid + j * 256;
            int row = u >> 2, ch = u & 3;
            cpasync16(aB + swz(row, ch), As + (size_t)(bm0 + row) * KP + kloc + ch * 8);
        }
#pragma unroll
        for (int j = 0; j < 4; j++) {
            int u = tid + j * 256;
            int row = u >> 2, ch = u & 3;
            cpasync16(bB + swz(row, ch), Bs + (size_t)(bn0 + row) * KP + kloc + ch * 8);
        }
        asm volatile("cp.async.commit_group;");
    };

    load_stage(0, 0);
    load_stage(1, 1);

    const int rit = (lane & 7) + ((lane >> 3) & 1) * 8;

    for (int cidx = 0; cidx < NCHUNK; cidx++) {
        const int st = cidx % 3;
        if (cidx < NCHUNK - 1) asm volatile("cp.async.wait_group 1;");
        else                   asm volatile("cp.async.wait_group 0;");
        __syncthreads();
        if (cidx + 2 < NCHUNK) load_stage(cidx + 2, (cidx + 2) % 3);

        const uint32_t aB = sb + st * STAGE_B;
        const uint32_t bB = aB + A_BYTES;
#pragma unroll
        for (int ks = 0; ks < 2; ks++) {
            const int kch = ks * 2 + (lane >> 4);
            uint32_t a[4][4], b[4][4];
#pragma unroll
            for (int mi = 0; mi < 4; mi++) {
                int r = warp_m * 64 + mi * 16 + rit;
                ldmatrix_x4(a[mi], aB + swz(r, kch));
            }
#pragma unroll
            for (int nj = 0; nj < 4; nj++) {
                int r = warp_n * 64 + nj * 16 + rit;
                ldmatrix_x4(b[nj], bB + swz(r, kch));
            }
#pragma unroll
            for (int mi = 0; mi < 4; mi++)
#pragma unroll
                for (int nj = 0; nj < 4; nj++) {
                    mma_bf16(c[mi][2 * nj],     a[mi], b[nj][0], b[nj][2]);
                    mma_bf16(c[mi][2 * nj + 1], a[mi], b[nj][1], b[nj][3]);
                }
        }
        __syncthreads();
    }

#pragma unroll
    for (int mi = 0; mi < 4; mi++) {
        const int r0 = bm0 + warp_m * 64 + mi * 16 + (lane >> 2);
#pragma unroll
        for (int nj = 0; nj < 4; nj++) {
#pragma unroll
            for (int h = 0; h < 2; h++) {
                const float* cc = c[mi][2 * nj + h];
                const int col = bn0 + warp_n * 64 + nj * 16 + h * 8 + (lane & 3) * 2;
                *(float2*)&g_P[(size_t)r0 * NCOLS + col]       = make_float2(cc[0], cc[1]);
                *(float2*)&g_P[(size_t)(r0 + 8) * NCOLS + col] = make_float2(cc[2], cc[3]);
            }
        }
    }
}

// ================= K2: tap-combine + bias + ReLU + L2-normalize (bf16 split out) =====
__global__ void k2_combine(const float* __restrict__ cb1,
                           const float* __restrict__ cb2,
                           const float* __restrict__ cb3)
{
    const int r = blockIdx.x;
    const int c = threadIdx.x;
    int l, L, rr;
    const bool isq = (r < QROWS);
    if (isq) { rr = r;          l = r % Q_;  L = Q_; }
    else     { rr = r - QROWS;  l = rr % D_; L = D_; }

    const float* Pr = g_P + (size_t)r * NCOLS;
    float v1 = cb1[c] + Pr[c];
    float v2 = cb2[c] + Pr[128 + c];
    float v3 = cb3[c] + Pr[384 + c];
    if (l + 1 < L) { v2 += Pr[NCOLS + 256 + c]; v3 += Pr[NCOLS + 512 + c]; }
    if (l + 2 < L) { v3 += Pr[2 * NCOLS + 640 + c]; }
    v1 = fmaxf(v1, 0.f); v2 = fmaxf(v2, 0.f); v3 = fmaxf(v3, 0.f);

    float s1 = v1 * v1, s2 = v2 * v2, s3 = v3 * v3;
#pragma unroll
    for (int o = 16; o; o >>= 1) {
        s1 += __shfl_xor_sync(0xffffffffu, s1, o);
        s2 += __shfl_xor_sync(0xffffffffu, s2, o);
        s3 += __shfl_xor_sync(0xffffffffu, s3, o);
    }
    __shared__ float sred[3][4];
    const int lane = c & 31, w = c >> 5;
    if (lane == 0) { sred[0][w] = s1; sred[1][w] = s2; sred[2][w] = s3; }
    __syncthreads();
    float ss1 = sred[0][0] + sred[0][1] + sred[0][2] + sred[0][3];
    float ss2 = sred[1][0] + sred[1][1] + sred[1][2] + sred[1][3];
    float ss3 = sred[2][0] + sred[2][1] + sred[2][2] + sred[2][3];
    float n1 = v1 * (1.0f / (sqrtf(ss1) + 1e-13f));
    float n2 = v2 * (1.0f / (sqrtf(ss2) + 1e-13f));
    float n3 = v3 * (1.0f / (sqrtf(ss3) + 1e-13f));

    float nv[3] = {n1, n2, n3};
#pragma unroll
    for (int t = 0; t < 3; t++) {
        __nv_bfloat16 h = __float2bfloat16(nv[t]);
        __nv_bfloat16 lo = __float2bfloat16(nv[t] - __bfloat162float(h));
        if (isq) {
            size_t o = ((size_t)t * QROWS + rr) * C_ + c;
            g_qnh[o] = h; g_qnl[o] = lo;
        } else {
            size_t o = ((size_t)t * DROWS + rr) * C_ + c;
            g_dnh[o] = h; g_dnl[o] = lo;
        }
    }
}

// ================= K3: HMMA cosine GEMM + chain-RBF + log pooling =================
// 512 threads = 16 warps; warp (mi = wid>>3, wn = wid&7) -> tile M16 x N32.
// q tile (32x128 hi+lo) resident; d streamed in 4 k-chunks of 32 (double-buffered).
// smem bytes: qhi 8192 | qlo 8192 | dbuf[2][hi 16384 + lo 16384] | spk 1408 | qm 128 | dm 1024
#define K3Q_HI   0
#define K3Q_LO   8192
#define K3D      16384
#define K3SPK    81920
#define K3QM     83328
#define K3DM     83456
#define K3_SMEM  84480

__global__ __launch_bounds__(512, 1) void k3h(const int* __restrict__ qtok,
                                              const int* __restrict__ dtok)
{
    extern __shared__ char smem[];
    const uint32_t sb = smem_u32(smem);
    float* spk = (float*)(smem + K3SPK);
    float* qm  = (float*)(smem + K3QM);
    float* dm  = (float*)(smem + K3DM);

    const int b = blockIdx.x, pair = blockIdx.y;
    const int qi3 = pair / 3, dj3 = pair % 3;
    const int tid = threadIdx.x, lane = tid & 31, wid = tid >> 5;
    const int mi = wid >> 3, wn = wid & 7;

    if (tid < 352) spk[tid] = 0.f;
    if (tid < 32) qm[tid] = (tid < Q_ && qtok[b * Q_ + tid] > 0) ? 1.f : 0.f;
    else if (tid < 288) { int d = tid - 32; dm[d] = (d < D_ && dtok[b * D_ + d] > 0) ? 1.f : 0.f; }

    const __nv_bfloat16* qh = g_qnh + ((size_t)qi3 * QROWS + b * Q_) * C_;
    const __nv_bfloat16* qlp = g_qnl + ((size_t)qi3 * QROWS + b * Q_) * C_;
    const __nv_bfloat16* dh = g_dnh + ((size_t)dj3 * DROWS + b * D_) * C_;
    const __nv_bfloat16* dl = g_dnl + ((size_t)dj3 * DROWS + b * D_) * C_;

    // q loads (part of chunk-0 group): 512 units = [4 kc][32 row][4 ch16]
    {
        int kc = tid >> 7, row = (tid >> 2) & 31, ch = tid & 3;
        int sz = (row < Q_) ? 16 : 0;
        int srow = (row < Q_) ? row : 0;
        size_t so = (size_t)srow * C_ + kc * 32 + ch * 8;
        uint32_t dst = sb + kc * 2048 + swz(row, ch);
        cpasync16z(dst,          qh  + so, sz);
        cpasync16z(dst + K3Q_LO, qlp + so, sz);
    }

    auto load_d = [&](int kc, int buf) {
#pragma unroll
        for (int j = 0; j < 2; j++) {
            int u = tid + j * 512;             // 0..1023 : 256 rows x 4 ch16
            int row = u >> 2, ch = u & 3;
            int sz = (row < D_) ? 16 : 0;
            int srow = (row < D_) ? row : 0;
            size_t so = (size_t)srow * C_ + kc * 32 + ch * 8;
            uint32_t dst = sb + K3D + buf * 32768 + swz(row, ch);
            cpasync16z(dst,          dh + so, sz);
            cpasync16z(dst + 16384,  dl + so, sz);
        }
        asm volatile("cp.async.commit_group;");
    };

    load_d(0, 0);

    float c[4][4];
#pragma unroll
    for (int i = 0; i < 4; i++)
#pragma unroll
        for (int j = 0; j < 4; j++) c[i][j] = 0.f;

    const int rit = (lane & 7) + ((lane >> 3) & 1) * 8;

    for (int kc = 0; kc < 4; kc++) {
        if (kc < 3) load_d(kc + 1, (kc + 1) & 1);
        if (kc < 3) asm volatile("cp.async.wait_group 1;");
        else        asm volatile("cp.async.wait_group 0;");
        __syncthreads();
        const uint32_t dbB = sb + K3D + (kc & 1) * 32768;
#pragma unroll
        for (int pass = 0; pass < 3; pass++) {
            const uint32_t qB = sb + ((pass == 2) ? K3Q_LO : K3Q_HI) + kc * 2048;
            const uint32_t dB = dbB + ((pass == 1) ? 16384 : 0);
#pragma unroll
            for (int ks = 0; ks < 2; ks++) {
                int kch = ks * 2 + (lane >> 4);
                uint32_t a[4], b0[4], b1[4];
                ldmatrix_x4(a,  qB + swz(mi * 16 + rit, kch));
                ldmatrix_x4(b0, dB + swz(wn * 32 + rit, kch));
                ldmatrix_x4(b1, dB + swz(wn * 32 + 16 + rit, kch));
                mma_bf16(c[0], a, b0[0], b0[2]);
                mma_bf16(c[1], a, b0[1], b0[3]);
                mma_bf16(c[2], a, b1[0], b1[2]);
                mma_bf16(c[3], a, b1[1], b1[3]);
            }
        }
        __syncthreads();
    }

    // ---- RBF on accumulators ----
    const float K20 = 28.853901f;       //  20*log2(e)
    const float AW  = -72.134754f;      // -50*log2(e)
    const float A0  = -7.2134754e8f;    // -5e5*log2(e)
    const u64 C4  = dupf(1.8315639e-2f);
    const u64 C8  = dupf(3.3546262e-4f);
    const u64 C12 = dupf(6.1442124e-6f);
    const u64 C16 = dupf(1.1253517e-7f);

#pragma unroll
    for (int s = 0; s < 2; s++) {
        const int row = mi * 16 + (lane >> 2) + s * 8;
        const float qmr = qm[row];
        float pk0 = 0.f;
        u64 pk56 = 0, pk47 = 0, pk38 = 0, pk29 = 0, pk110 = 0;
#pragma unroll
        for (int nj = 0; nj < 4; nj++) {
#pragma unroll
            for (int h = 0; h < 2; h++) {
                float v = c[nj][2 * s + h];
                int col = wn * 32 + nj * 8 + (lane & 3) * 2 + h;
                float m = qmr * dm[col];
                float cm = v * m;
                float arg = cm * K20;
                float t  = ex2f(arg);
                float ti = ex2f(-arg);
                u64 tt = packf(t, ti);
                float dlt = cm - 0.1f;
                float gl = ex2f(dlt * dlt * AW);
                u64 ab = packf(gl, gl * ti);
                u64 m2 = dupf(m);
                ffma2(pk56, m2, ab);
                ab = mul2(ab, tt); ab = mul2(ab, C4);  ffma2(pk47, m2, ab);
                ab = mul2(ab, tt); ab = mul2(ab, C8);  ffma2(pk38, m2, ab);
                ab = mul2(ab, tt); ab = mul2(ab, C12); ffma2(pk29, m2, ab);
                ab = mul2(ab, tt); ab = mul2(ab, C16); ffma2(pk110, m2, ab);
                float d1 = cm - 1.f;
                pk0 = fmaf(m, ex2f(d1 * d1 * A0), pk0);
            }
        }
#pragma unroll
        for (int o = 1; o <= 2; o <<= 1) {
            pk0  += __shfl_xor_sync(0xffffffffu, pk0, o);
            pk56  = add2(pk56,  __shfl_xor_sync(0xffffffffu, pk56, o));
            pk47  = add2(pk47,  __shfl_xor_sync(0xffffffffu, pk47, o));
            pk38  = add2(pk38,  __shfl_xor_sync(0xffffffffu, pk38, o));
            pk29  = add2(pk29,  __shfl_xor_sync(0xffffffffu, pk29, o));
            pk110 = add2(pk110, __shfl_xor_sync(0xffffffffu, pk110, o));
        }
        if ((lane & 3) == 0) {
            float lo, hi;
            float* rw = spk + row * 11;
            atomicAdd(&rw[0], pk0);
            unpackf(pk56,  lo, hi); atomicAdd(&rw[5], lo); atomicAdd(&rw[6],  hi);
            unpackf(pk47,  lo, hi); atomicAdd(&rw[4], lo); atomicAdd(&rw[7],  hi);
            unpackf(pk38,  lo, hi); atomicAdd(&rw[3], lo); atomicAdd(&rw[8],  hi);
            unpackf(pk29,  lo, hi); atomicAdd(&rw[2], lo); atomicAdd(&rw[9],  hi);
            unpackf(pk110, lo, hi); atomicAdd(&rw[1], lo); atomicAdd(&rw[10], hi);
        }
    }
    __syncthreads();

    if (tid < 11) {
        float f = 0.f;
        for (int q = 0; q < Q_; q++)
            f += logf(fmaxf(spk[q * 11 + tid], 1e-10f)) * 0.01f * qm[q];
        g_feats[(b * 9 + pair) * 11 + tid] = f;
    }
}

// ================= K4: final dense =================
__global__ void k4_out(const float* __restrict__ dw, float* __restrict__ out)
{
    int b = threadIdx.x;
    float f = 0.f;
#pragma unroll
    for (int j = 0; j < 99; j++) f += g_feats[b * 99 + j] * dw[j];
    out[b] = f;
}

// ================= launch =================
extern "C" void kernel_launch(void* const* d_in, const int* in_sizes, int n_in,
                              void* d_out, int out_size)
{
    (void)in_sizes; (void)n_in; (void)out_size;
    const int*   qtok = (const int*)d_in[0];
    const int*   dtok = (const int*)d_in[1];
    const float* emb  = (const float*)d_in[2];
    const float* w1   = (const float*)d_in[3];
    const float* w2   = (const float*)d_in[4];
    const float* w3   = (const float*)d_in[5];
    const float* cb1  = (const float*)d_in[6];
    const float* cb2  = (const float*)d_in[7];
    const float* cb3  = (const float*)d_in[8];
    const float* dw   = (const float*)d_in[9];
    float* out = (float*)d_out;

    cudaFuncSetAttribute(k1h, cudaFuncAttributeMaxDynamicSharedMemorySize, K1_SMEM);
    cudaFuncSetAttribute(k3h, cudaFuncAttributeMaxDynamicSharedMemorySize, K3_SMEM);

    pack_all<<<WBLOCKS + ABLOCKS, 256>>>(w1, w2, w3, emb, qtok, dtok);
    k1h<<<dim3(230, 3), 256, K1_SMEM>>>();
    k2_combine<<<NROWS, 128>>>(cb1, cb2, cb3);
    k3h<<<dim3(128, 9), 512, K3_SMEM>>>(qtok, dtok);
    k4_out<<<1, 128>>>(dw, out);
}